// round 7
// baseline (speedup 1.0000x reference)
#include <cuda_runtime.h>
#include <cuda_bf16.h>

#define B_ 8
#define P_ 4096
#define G_ 96
#define NT 256
#define NW (NT / 32)
#define CPT (P_ / NT)
#define BIGF 1e9f
#define INFF 3.402823466e+38f

__device__ unsigned long long g_rowarg[B_ * G_];   // packed (f2ord(min)<<32) | argmin_p

__device__ __forceinline__ unsigned int f2ord(float f) {
    unsigned int u = __float_as_uint(f);
    return ((int)u < 0) ? ~u : (u ^ 0x80000000u);
}
__device__ __forceinline__ float ord2f(unsigned int k) {
    unsigned int u = (k & 0x80000000u) ? (k ^ 0x80000000u) : ~k;
    return __uint_as_float(u);
}

// ---------------------------------------------------------------------------
// Kernel 0: init g_rowarg to +inf keys
// ---------------------------------------------------------------------------
__global__ void rowarg_init_kernel() {
    g_rowarg[threadIdx.x] = 0xffffffffffffffffull;
}

// ---------------------------------------------------------------------------
// Kernel 1: single streaming pass over cd/gi (original [B,P,G] layout),
// per-(b,g) argmin of cost = cd - 2*gi.  No transposed matrix materialized.
// block = (24,16): tx indexes float4 along g (24*4=96), ty strides p.
// grid = (P_/128, B_): each block covers 128 consecutive p (contiguous 48KB x2).
// ---------------------------------------------------------------------------
#define MPP 8   /* p-iterations per thread: 16 ty * 8 = 128 p per block */
__global__ __launch_bounds__(384, 4)
void fused_min_kernel(const float* __restrict__ cd,
                      const float* __restrict__ gi) {
    __shared__ unsigned long long red[G_][17];   // [g][ty] (pad col to 17 vs bank)
    const int b  = blockIdx.y;
    const int p0 = blockIdx.x * 128;
    const int tx = threadIdx.x;                  // 0..23
    const int ty = threadIdx.y;                  // 0..15

    unsigned long long best[4];
    #pragma unroll
    for (int l = 0; l < 4; l++) best[l] = 0xffffffffffffffffull;

    const size_t base = ((size_t)b * P_ + p0) * G_ + 4 * tx;
    #pragma unroll
    for (int k = 0; k < MPP; k++) {
        const int p = ty + 16 * k;               // ascending p per thread
        const size_t idx = base + (size_t)p * G_;
        float4 c4 = __ldg((const float4*)(cd + idx));
        float4 g4 = __ldg((const float4*)(gi + idx));
        float val[4] = { c4.x - 2.0f * g4.x, c4.y - 2.0f * g4.y,
                         c4.z - 2.0f * g4.z, c4.w - 2.0f * g4.w };
        #pragma unroll
        for (int l = 0; l < 4; l++) {
            unsigned long long pk =
                ((unsigned long long)f2ord(val[l]) << 32) | (unsigned int)(p0 + p);
            if (pk < best[l]) best[l] = pk;
        }
    }
    #pragma unroll
    for (int l = 0; l < 4; l++) red[4 * tx + l][ty] = best[l];
    __syncthreads();

    // 384 threads, 96 g-rows: thread t<96 reduces its row's 16 partials
    const int t = tx + 24 * ty;
    if (t < G_) {
        unsigned long long m = red[t][0];
        #pragma unroll
        for (int w = 1; w < 16; w++) if (red[t][w] < m) m = red[t][w];
        atomicMin(&g_rowarg[b * G_ + t], m);
    }
}

// ---------------------------------------------------------------------------
// Kernel 2: one block per batch. Greedy dual-feasible init (u[i]=rowmin, v=0),
// then JV shortest augmenting path for conflicted rows, reading cd/gi strided.
// ---------------------------------------------------------------------------
__global__ __launch_bounds__(NT, 1)
void matcher_kernel(const float* __restrict__ cd,
                    const float* __restrict__ gi,
                    const int* __restrict__ nactual,
                    float* __restrict__ out) {
    extern __shared__ char smem[];
    int*   row4col  = (int*)smem;                      // [P_]
    float* sh_dump  = (float*)(row4col + P_);          // [P_]
    int*   path_dump= (int*)(sh_dump + P_);            // [P_] (aliased as colowner)
    float* u        = (float*)(path_dump + P_);        // [G_]
    int*   col4row  = (int*)(u + G_);                  // [G_]
    uint4* partials = (uint4*)(col4row + G_);          // [2][NW]
    unsigned char* SR = (unsigned char*)(partials + 2 * NW); // [G_]

    const int b = blockIdx.x;
    const int t = threadIdx.x;
    const float* cdb = cd + (size_t)b * P_ * G_;
    const float* gib = gi + (size_t)b * P_ * G_;
    const int nact = nactual[b];

    float vreg[CPT];
    float shreg[CPT];
    int   pathreg[CPT];
    unsigned int scmask;

    #pragma unroll
    for (int k = 0; k < CPT; k++) vreg[k] = 0.0f;
    int* colowner = path_dump;
    for (int j = t; j < P_; j += NT) { row4col[j] = -1; colowner[j] = 0x7fffffff; }
    if (t < G_) col4row[t] = -1;
    __syncthreads();

    // ---- greedy phase: row i wants its argmin column; lowest row index wins ----
    unsigned long long myarg = 0;
    if (t < G_ && t < nact) {
        myarg = g_rowarg[b * G_ + t];
        u[t] = ord2f((unsigned int)(myarg >> 32));     // u[i] = row min (exact)
        atomicMin(&colowner[(int)(myarg & 0xffffffffu)], t);
    }
    __syncthreads();
    if (t < G_ && t < nact) {
        int j = (int)(myarg & 0xffffffffu);
        if (colowner[j] == t) { col4row[t] = j; row4col[j] = t; }
    }
    __syncthreads();

    // ---- augment the (rare) unassigned rows ----
    for (int i = 0; i < nact; ++i) {
        if (col4row[i] >= 0) continue;

        #pragma unroll
        for (int k = 0; k < CPT; k++) { shreg[k] = BIGF; pathreg[k] = -1; }
        scmask = 0u;
        if (t < G_) SR[t] = 0;
        __syncthreads();           // barrier A

        int   cur    = i;
        float ucur   = u[i];
        float minval = 0.0f;
        int   sink   = -1;
        int   parity = 0;

        while (sink < 0) {
            if (t == 0) SR[cur] = 1;

            // strided gather of cost row `cur` from original layout
            float c[CPT];
            #pragma unroll
            for (int k = 0; k < CPT; k++) {
                const size_t idx = (size_t)(t + k * NT) * G_ + cur;
                c[k] = __ldg(cdb + idx) - 2.0f * __ldg(gib + idx);
            }

            float bestv = INFF;
            int   bestj = P_;
            #pragma unroll
            for (int k = 0; k < CPT; k++) {
                if (!((scmask >> k) & 1u)) {
                    float red = ((minval + c[k]) - ucur) - vreg[k];
                    if (red < shreg[k]) { shreg[k] = red; pathreg[k] = cur; }
                    if (shreg[k] < bestv) { bestv = shreg[k]; bestj = t + k * NT; }
                }
            }
            unsigned int key    = f2ord(bestv);
            unsigned int minkey = __reduce_min_sync(0xffffffffu, key);
            unsigned int jc     = (key == minkey) ? (unsigned int)bestj : 0xffffffffu;
            unsigned int minj   = __reduce_min_sync(0xffffffffu, jc);

            if ((t & 31) == 0) {
                int r = row4col[minj];
                float ur = (r >= 0) ? u[r] : 0.0f;
                partials[parity * NW + (t >> 5)] =
                    make_uint4(minkey, minj, (unsigned int)r, __float_as_uint(ur));
            }
            __syncthreads();

            uint4 best = partials[parity * NW];
            #pragma unroll
            for (int w = 1; w < NW; w++) {
                uint4 pw = partials[parity * NW + w];
                if (pw.x < best.x || (pw.x == best.x && pw.y < best.y)) best = pw;
            }
            minval = ord2f(best.x);
            int bj = (int)best.y;
            if ((bj & (NT - 1)) == t) scmask |= 1u << (bj >> 8);
            if ((int)best.z < 0) { sink = bj; }
            else { cur = (int)best.z; ucur = __uint_as_float(best.w); }
            parity ^= 1;
        }

        #pragma unroll
        for (int k = 0; k < CPT; k++) {
            sh_dump[t + k * NT]   = shreg[k];
            path_dump[t + k * NT] = pathreg[k];
        }
        __syncthreads();           // barrier B

        // dual updates (standard JV, valid for arbitrary feasible starting duals)
        if (t == 0) u[i] += minval;
        if (t < G_ && t != i && SR[t]) {
            int c4 = col4row[t]; if (c4 < 0) c4 = 0;
            u[t] = (u[t] + minval) - sh_dump[c4];
        }
        #pragma unroll
        for (int k = 0; k < CPT; k++)
            if ((scmask >> k) & 1u) vreg[k] = vreg[k] - (minval - shreg[k]);
        __syncthreads();           // barrier C

        if (t == 0) {
            int j = sink;
            while (true) {
                int r = path_dump[j];
                row4col[j] = r;
                int jn = col4row[r];
                col4row[r] = j;
                if (r == i) break;
                j = jn;
            }
        }
        __syncthreads();           // make augment visible before next row's test
    }

    // outputs: region 0 = per_prop_gt_inds (as float), region 1 = matched mask
    float* oi = out + (size_t)b * P_;
    float* om = out + (size_t)B_ * P_ + (size_t)b * P_;
    for (int j = t; j < P_; j += NT) { oi[j] = 0.0f; om[j] = 0.0f; }
    __syncthreads();
    if (t < G_ && t < nact) {
        int p = col4row[t];
        if (p >= 0) { oi[p] = (float)t; om[p] = 1.0f; }
    }
}

// ---------------------------------------------------------------------------
static const int MATCHER_SMEM =
    P_ * 4 * 3                 /* row4col, sh_dump, path_dump/colowner */
    + G_ * 4 * 2               /* u, col4row */
    + 2 * NW * 16              /* uint4 partials */
    + G_ + 64;                 /* SR + pad */

extern "C" void kernel_launch(void* const* d_in, const int* in_sizes, int n_in,
                              void* d_out, int out_size) {
    const float* cd   = (const float*)d_in[0];
    const float* gi   = (const float*)d_in[1];
    const int*   nact = (const int*)d_in[2];

    float* out = (float*)d_out;                  // [2, B, P] float32

    rowarg_init_kernel<<<1, B_ * G_>>>();

    dim3 tb(24, 16);
    dim3 gb(P_ / 128, B_);
    fused_min_kernel<<<gb, tb>>>(cd, gi);

    cudaFuncSetAttribute(matcher_kernel,
                         cudaFuncAttributeMaxDynamicSharedMemorySize, MATCHER_SMEM);
    matcher_kernel<<<B_, NT, MATCHER_SMEM>>>(cd, gi, nact, out);
}

// round 8
// speedup vs baseline: 1.3198x; 1.3198x over previous
#include <cuda_runtime.h>
#include <cuda_bf16.h>

#define B_ 8
#define P_ 4096
#define G_ 96
#define NT 256
#define NW (NT / 32)
#define CPT (P_ / NT)
#define PBLK 64                 /* p-blocks of 64 in transpose */
#define BIGF 1e9f
#define INFF 3.402823466e+38f

__device__ float g_costT[(size_t)B_ * G_ * P_];
__device__ unsigned long long g_part[B_ * G_ * PBLK];   // per-block packed mins
__device__ unsigned long long g_rowarg[B_ * G_];        // (f2ord(min)<<32)|argmin_p

__device__ __forceinline__ unsigned int f2ord(float f) {
    unsigned int u = __float_as_uint(f);
    return ((int)u < 0) ? ~u : (u ^ 0x80000000u);
}
__device__ __forceinline__ float ord2f(unsigned int k) {
    unsigned int u = (k & 0x80000000u) ? (k ^ 0x80000000u) : ~k;
    return __uint_as_float(u);
}

// ---------------------------------------------------------------------------
// Kernel 1: fused cost + transpose (64p x 32g tile, 8 elems/thread) + per-block
// row-min partials.  costT[b][g][p] = cd[b][p][g] - 2*gi[b][p][g]
// grid = (P_/64, G_/32, B_), block = (32, 8)
// ---------------------------------------------------------------------------
__global__ __launch_bounds__(256, 4)
void cost_transpose_kernel(const float* __restrict__ cd,
                           const float* __restrict__ gi) {
    __shared__ float tile[64][33];
    __shared__ unsigned long long pmin[32][8];
    const int b  = blockIdx.z;
    const int p0 = blockIdx.x * 64;
    const int g0 = blockIdx.y * 32;
    const int tx = threadIdx.x;              // 0..31 -> g lane
    const int ty = threadIdx.y;              // 0..7  -> p lane

    // load 8 p-rows per thread (one g-column), coalesced along g
    float c[8], g[8];
    #pragma unroll
    for (int r = 0; r < 8; r++) {
        size_t iidx = ((size_t)b * P_ + (p0 + ty + 8 * r)) * G_ + (g0 + tx);
        c[r] = __ldg(cd + iidx);
        g[r] = __ldg(gi + iidx);
    }
    unsigned long long best = 0xffffffffffffffffull;
    #pragma unroll
    for (int r = 0; r < 8; r++) {
        float val = c[r] - 2.0f * g[r];      // 2*g exact in fp32
        tile[ty + 8 * r][tx] = val;
        unsigned long long pk =
            ((unsigned long long)f2ord(val) << 32) | (unsigned int)(p0 + ty + 8 * r);
        if (pk < best) best = pk;
    }
    pmin[tx][ty] = best;
    __syncthreads();

    // write transposed, coalesced along p (8 stores/thread)
    #pragma unroll
    for (int rr = 0; rr < 4; rr++)
        #pragma unroll
        for (int h = 0; h < 2; h++)
            g_costT[((size_t)b * G_ + (g0 + ty + 8 * rr)) * P_ + (p0 + tx + 32 * h)]
                = tile[tx + 32 * h][ty + 8 * rr];

    // warp 0 reduces the 8 ty-partials per g and writes the block partial
    if (ty == 0) {
        unsigned long long m = pmin[tx][0];
        #pragma unroll
        for (int w = 1; w < 8; w++) if (pmin[tx][w] < m) m = pmin[tx][w];
        g_part[((size_t)b * G_ + (g0 + tx)) * PBLK + blockIdx.x] = m;
    }
}

// ---------------------------------------------------------------------------
// Kernel 2: reduce 64 partials per (b,g) into g_rowarg. grid=(G_,B_), block=64.
// ---------------------------------------------------------------------------
__global__ __launch_bounds__(64, 16)
void part_reduce_kernel() {
    __shared__ unsigned long long w2[2];
    const int g = blockIdx.x, b = blockIdx.y;
    const int t = threadIdx.x;
    unsigned long long m = g_part[((size_t)b * G_ + g) * PBLK + t];
    #pragma unroll
    for (int off = 16; off; off >>= 1) {
        unsigned long long o = __shfl_down_sync(0xffffffffu, m, off);
        if (o < m) m = o;
    }
    if ((t & 31) == 0) w2[t >> 5] = m;
    __syncthreads();
    if (t == 0) {
        m = (w2[1] < w2[0]) ? w2[1] : w2[0];
        g_rowarg[b * G_ + g] = m;
    }
}

// ---------------------------------------------------------------------------
// Kernel 3: one block per batch. Greedy dual-feasible init (u[i]=rowmin, v=0),
// then JV shortest augmenting path only for conflicted rows.
// ---------------------------------------------------------------------------
__global__ __launch_bounds__(NT, 1)
void matcher_kernel(const int* __restrict__ nactual,
                    float* __restrict__ out) {
    extern __shared__ char smem[];
    int*   row4col  = (int*)smem;                      // [P_]
    float* sh_dump  = (float*)(row4col + P_);          // [P_]
    int*   path_dump= (int*)(sh_dump + P_);            // [P_] (aliased as colowner)
    float* u        = (float*)(path_dump + P_);        // [G_]
    int*   col4row  = (int*)(u + G_);                  // [G_]
    uint4* partials = (uint4*)(col4row + G_);          // [2][NW]
    unsigned char* SR = (unsigned char*)(partials + 2 * NW); // [G_]

    const int b = blockIdx.x;
    const int t = threadIdx.x;
    const float* cost = g_costT + (size_t)b * G_ * P_;
    const int nact = nactual[b];

    float vreg[CPT];
    float shreg[CPT];
    int   pathreg[CPT];
    unsigned int scmask;

    #pragma unroll
    for (int k = 0; k < CPT; k++) vreg[k] = 0.0f;
    int* colowner = path_dump;
    for (int j = t; j < P_; j += NT) { row4col[j] = -1; colowner[j] = 0x7fffffff; }
    if (t < G_) col4row[t] = -1;
    __syncthreads();

    // ---- greedy phase: row i wants its argmin column; lowest row index wins ----
    unsigned long long myarg = 0;
    if (t < G_ && t < nact) {
        myarg = g_rowarg[b * G_ + t];
        u[t] = ord2f((unsigned int)(myarg >> 32));     // u[i] = row min (exact)
        atomicMin(&colowner[(int)(myarg & 0xffffffffu)], t);
    }
    __syncthreads();
    if (t < G_ && t < nact) {
        int j = (int)(myarg & 0xffffffffu);
        if (colowner[j] == t) { col4row[t] = j; row4col[j] = t; }
    }
    __syncthreads();

    // ---- augment the (rare) unassigned rows ----
    for (int i = 0; i < nact; ++i) {
        if (col4row[i] >= 0) continue;

        #pragma unroll
        for (int k = 0; k < CPT; k++) { shreg[k] = BIGF; pathreg[k] = -1; }
        scmask = 0u;
        if (t < G_) SR[t] = 0;
        __syncthreads();           // barrier A

        int   cur    = i;
        float ucur   = u[i];
        float minval = 0.0f;
        int   sink   = -1;
        int   parity = 0;

        while (sink < 0) {
            if (t == 0) SR[cur] = 1;
            const float* crow = cost + (size_t)cur * P_;

            float c[CPT];
            #pragma unroll
            for (int k = 0; k < CPT; k++) c[k] = __ldg(crow + t + k * NT);

            float bestv = INFF;
            int   bestj = P_;
            #pragma unroll
            for (int k = 0; k < CPT; k++) {
                if (!((scmask >> k) & 1u)) {
                    float red = ((minval + c[k]) - ucur) - vreg[k];
                    if (red < shreg[k]) { shreg[k] = red; pathreg[k] = cur; }
                    if (shreg[k] < bestv) { bestv = shreg[k]; bestj = t + k * NT; }
                }
            }
            unsigned int key    = f2ord(bestv);
            unsigned int minkey = __reduce_min_sync(0xffffffffu, key);
            unsigned int jc     = (key == minkey) ? (unsigned int)bestj : 0xffffffffu;
            unsigned int minj   = __reduce_min_sync(0xffffffffu, jc);

            if ((t & 31) == 0) {
                int r = row4col[minj];
                float ur = (r >= 0) ? u[r] : 0.0f;
                partials[parity * NW + (t >> 5)] =
                    make_uint4(minkey, minj, (unsigned int)r, __float_as_uint(ur));
            }
            __syncthreads();

            uint4 best = partials[parity * NW];
            #pragma unroll
            for (int w = 1; w < NW; w++) {
                uint4 pw = partials[parity * NW + w];
                if (pw.x < best.x || (pw.x == best.x && pw.y < best.y)) best = pw;
            }
            minval = ord2f(best.x);
            int bj = (int)best.y;
            if ((bj & (NT - 1)) == t) scmask |= 1u << (bj >> 8);
            if ((int)best.z < 0) { sink = bj; }
            else { cur = (int)best.z; ucur = __uint_as_float(best.w); }
            parity ^= 1;
        }

        #pragma unroll
        for (int k = 0; k < CPT; k++) {
            sh_dump[t + k * NT]   = shreg[k];
            path_dump[t + k * NT] = pathreg[k];
        }
        __syncthreads();           // barrier B

        if (t == 0) u[i] += minval;
        if (t < G_ && t != i && SR[t]) {
            int c4 = col4row[t]; if (c4 < 0) c4 = 0;
            u[t] = (u[t] + minval) - sh_dump[c4];
        }
        #pragma unroll
        for (int k = 0; k < CPT; k++)
            if ((scmask >> k) & 1u) vreg[k] = vreg[k] - (minval - shreg[k]);
        __syncthreads();           // barrier C

        if (t == 0) {
            int j = sink;
            while (true) {
                int r = path_dump[j];
                row4col[j] = r;
                int jn = col4row[r];
                col4row[r] = j;
                if (r == i) break;
                j = jn;
            }
        }
        __syncthreads();
    }

    // outputs: region 0 = per_prop_gt_inds (as float), region 1 = matched mask
    float* oi = out + (size_t)b * P_;
    float* om = out + (size_t)B_ * P_ + (size_t)b * P_;
    for (int j = t; j < P_; j += NT) { oi[j] = 0.0f; om[j] = 0.0f; }
    __syncthreads();
    if (t < G_ && t < nact) {
        int p = col4row[t];
        if (p >= 0) { oi[p] = (float)t; om[p] = 1.0f; }
    }
}

// ---------------------------------------------------------------------------
static const int MATCHER_SMEM =
    P_ * 4 * 3                 /* row4col, sh_dump, path_dump/colowner */
    + G_ * 4 * 2               /* u, col4row */
    + 2 * NW * 16              /* uint4 partials */
    + G_ + 64;                 /* SR + pad */

extern "C" void kernel_launch(void* const* d_in, const int* in_sizes, int n_in,
                              void* d_out, int out_size) {
    const float* cd   = (const float*)d_in[0];
    const float* gi   = (const float*)d_in[1];
    const int*   nact = (const int*)d_in[2];

    float* out = (float*)d_out;                  // [2, B, P] float32

    dim3 tb(32, 8);
    dim3 gb(P_ / 64, G_ / 32, B_);
    cost_transpose_kernel<<<gb, tb>>>(cd, gi);

    part_reduce_kernel<<<dim3(G_, B_), 64>>>();

    cudaFuncSetAttribute(matcher_kernel,
                         cudaFuncAttributeMaxDynamicSharedMemorySize, MATCHER_SMEM);
    matcher_kernel<<<B_, NT, MATCHER_SMEM>>>(nact, out);
}

// round 9
// speedup vs baseline: 1.3651x; 1.0343x over previous
#include <cuda_runtime.h>
#include <cuda_bf16.h>

#define B_ 8
#define P_ 4096
#define G_ 96
#define NT 256
#define NW (NT / 32)
#define CPT (P_ / NT)
#define PBLK 128                /* p-tiles of 32 in transpose */
#define BIGF 1e9f
#define INFF 3.402823466e+38f

__device__ float g_costT[(size_t)B_ * G_ * P_];
__device__ unsigned long long g_part[(size_t)B_ * G_ * PBLK]; // per-tile packed mins

__device__ __forceinline__ unsigned int f2ord(float f) {
    unsigned int u = __float_as_uint(f);
    return ((int)u < 0) ? ~u : (u ^ 0x80000000u);
}
__device__ __forceinline__ float ord2f(unsigned int k) {
    unsigned int u = (k & 0x80000000u) ? (k ^ 0x80000000u) : ~k;
    return __uint_as_float(u);
}

// ---------------------------------------------------------------------------
// Kernel 1: fused cost + transpose (R6 geometry: 32x32 tile, 4 elems/thread)
// + per-tile row-min partial (float-domain min, packed once at the end).
// costT[b][g][p] = cd[b][p][g] - 2*gi[b][p][g].  grid=(P/32, G/32, B), blk=(32,8)
// ---------------------------------------------------------------------------
__global__ __launch_bounds__(256, 8)
void cost_transpose_kernel(const float* __restrict__ cd,
                           const float* __restrict__ gi) {
    __shared__ float tile[32][33];
    __shared__ unsigned long long pmin[32][8];
    const int b  = blockIdx.z;
    const int p0 = blockIdx.x * 32;
    const int g0 = blockIdx.y * 32;
    const int tx = threadIdx.x;              // g lane
    const int ty = threadIdx.y;              // p lane (0..7)

    float c[4], g[4];
    #pragma unroll
    for (int r = 0; r < 4; r++) {
        size_t iidx = ((size_t)b * P_ + (p0 + ty + 8 * r)) * G_ + (g0 + tx);
        c[r] = __ldg(cd + iidx);
        g[r] = __ldg(gi + iidx);
    }
    float bestv = INFF;
    int   bestp = 0;
    #pragma unroll
    for (int r = 0; r < 4; r++) {
        float val = c[r] - 2.0f * g[r];      // 2*g exact in fp32
        tile[ty + 8 * r][tx] = val;
        if (val < bestv) { bestv = val; bestp = p0 + ty + 8 * r; } // ascending p
    }
    pmin[tx][ty] = ((unsigned long long)f2ord(bestv) << 32) | (unsigned int)bestp;
    __syncthreads();

    #pragma unroll
    for (int r = 0; r < 4; r++)
        g_costT[((size_t)b * G_ + (g0 + ty + 8 * r)) * P_ + (p0 + tx)]
            = tile[tx][ty + 8 * r];

    if (ty == 0) {
        unsigned long long m = pmin[tx][0];
        #pragma unroll
        for (int w = 1; w < 8; w++) if (pmin[tx][w] < m) m = pmin[tx][w];
        g_part[((size_t)b * G_ + (g0 + tx)) * PBLK + blockIdx.x] = m;
    }
}

// ---------------------------------------------------------------------------
// Kernel 2: one block per batch.  (a) reduce 128 partials/row -> rowarg_s,
// (b) greedy dual-feasible init (u[i]=rowmin, v=0), (c) JV augmenting path
// for the rare conflicted rows.
// ---------------------------------------------------------------------------
__global__ __launch_bounds__(NT, 1)
void matcher_kernel(const int* __restrict__ nactual,
                    float* __restrict__ out) {
    extern __shared__ char smem[];
    unsigned long long* rowarg_s = (unsigned long long*)smem;   // [G_] (8B aligned)
    int*   row4col  = (int*)(rowarg_s + G_);           // [P_]
    float* sh_dump  = (float*)(row4col + P_);          // [P_]
    int*   path_dump= (int*)(sh_dump + P_);            // [P_] (aliased as colowner)
    float* u        = (float*)(path_dump + P_);        // [G_]
    int*   col4row  = (int*)(u + G_);                  // [G_]
    uint4* partials = (uint4*)(col4row + G_);          // [2][NW] (16B aligned)
    unsigned char* SR = (unsigned char*)(partials + 2 * NW); // [G_]

    const int b = blockIdx.x;
    const int t = threadIdx.x;
    const int wid = t >> 5, lane = t & 31;
    const float* cost = g_costT + (size_t)b * G_ * P_;
    const int nact = nactual[b];

    float vreg[CPT];
    float shreg[CPT];
    int   pathreg[CPT];
    unsigned int scmask;

    // (a) reduce partials: 8 warps x 12 rows
    #pragma unroll
    for (int rr = 0; rr < G_ / NW; rr++) {
        const int row = wid * (G_ / NW) + rr;
        const unsigned long long* pp = g_part + ((size_t)b * G_ + row) * PBLK;
        unsigned long long m = pp[lane];
        #pragma unroll
        for (int l = 1; l < PBLK / 32; l++) {
            unsigned long long o = pp[lane + 32 * l];
            if (o < m) m = o;
        }
        #pragma unroll
        for (int off = 16; off; off >>= 1) {
            unsigned long long o = __shfl_down_sync(0xffffffffu, m, off);
            if (o < m) m = o;
        }
        if (lane == 0) rowarg_s[row] = m;
    }

    #pragma unroll
    for (int k = 0; k < CPT; k++) vreg[k] = 0.0f;
    int* colowner = path_dump;
    for (int j = t; j < P_; j += NT) { row4col[j] = -1; colowner[j] = 0x7fffffff; }
    if (t < G_) col4row[t] = -1;
    __syncthreads();

    // (b) greedy: row i wants its argmin column; lowest row index wins
    unsigned long long myarg = 0;
    if (t < G_ && t < nact) {
        myarg = rowarg_s[t];
        u[t] = ord2f((unsigned int)(myarg >> 32));     // u[i] = row min (exact)
        atomicMin(&colowner[(int)(myarg & 0xffffffffu)], t);
    }
    __syncthreads();
    if (t < G_ && t < nact) {
        int j = (int)(myarg & 0xffffffffu);
        if (colowner[j] == t) { col4row[t] = j; row4col[j] = t; }
    }
    __syncthreads();

    // (c) augment the (rare) unassigned rows
    for (int i = 0; i < nact; ++i) {
        if (col4row[i] >= 0) continue;

        #pragma unroll
        for (int k = 0; k < CPT; k++) { shreg[k] = BIGF; pathreg[k] = -1; }
        scmask = 0u;
        if (t < G_) SR[t] = 0;
        __syncthreads();           // barrier A

        int   cur    = i;
        float ucur   = u[i];
        float minval = 0.0f;
        int   sink   = -1;
        int   parity = 0;

        while (sink < 0) {
            if (t == 0) SR[cur] = 1;
            const float* crow = cost + (size_t)cur * P_;

            float c[CPT];
            #pragma unroll
            for (int k = 0; k < CPT; k++) c[k] = __ldg(crow + t + k * NT);

            float bestv = INFF;
            int   bestj = P_;
            #pragma unroll
            for (int k = 0; k < CPT; k++) {
                if (!((scmask >> k) & 1u)) {
                    float red = ((minval + c[k]) - ucur) - vreg[k];
                    if (red < shreg[k]) { shreg[k] = red; pathreg[k] = cur; }
                    if (shreg[k] < bestv) { bestv = shreg[k]; bestj = t + k * NT; }
                }
            }
            unsigned int key    = f2ord(bestv);
            unsigned int minkey = __reduce_min_sync(0xffffffffu, key);
            unsigned int jc     = (key == minkey) ? (unsigned int)bestj : 0xffffffffu;
            unsigned int minj   = __reduce_min_sync(0xffffffffu, jc);

            if (lane == 0) {
                int r = row4col[minj];
                float ur = (r >= 0) ? u[r] : 0.0f;
                partials[parity * NW + wid] =
                    make_uint4(minkey, minj, (unsigned int)r, __float_as_uint(ur));
            }
            __syncthreads();

            uint4 best = partials[parity * NW];
            #pragma unroll
            for (int w = 1; w < NW; w++) {
                uint4 pw = partials[parity * NW + w];
                if (pw.x < best.x || (pw.x == best.x && pw.y < best.y)) best = pw;
            }
            minval = ord2f(best.x);
            int bj = (int)best.y;
            if ((bj & (NT - 1)) == t) scmask |= 1u << (bj >> 8);
            if ((int)best.z < 0) { sink = bj; }
            else { cur = (int)best.z; ucur = __uint_as_float(best.w); }
            parity ^= 1;
        }

        #pragma unroll
        for (int k = 0; k < CPT; k++) {
            sh_dump[t + k * NT]   = shreg[k];
            path_dump[t + k * NT] = pathreg[k];
        }
        __syncthreads();           // barrier B

        if (t == 0) u[i] += minval;
        if (t < G_ && t != i && SR[t]) {
            int c4 = col4row[t]; if (c4 < 0) c4 = 0;
            u[t] = (u[t] + minval) - sh_dump[c4];
        }
        #pragma unroll
        for (int k = 0; k < CPT; k++)
            if ((scmask >> k) & 1u) vreg[k] = vreg[k] - (minval - shreg[k]);
        __syncthreads();           // barrier C

        if (t == 0) {
            int j = sink;
            while (true) {
                int r = path_dump[j];
                row4col[j] = r;
                int jn = col4row[r];
                col4row[r] = j;
                if (r == i) break;
                j = jn;
            }
        }
        __syncthreads();
    }

    // outputs: region 0 = per_prop_gt_inds (as float), region 1 = matched mask
    float* oi = out + (size_t)b * P_;
    float* om = out + (size_t)B_ * P_ + (size_t)b * P_;
    for (int j = t; j < P_; j += NT) { oi[j] = 0.0f; om[j] = 0.0f; }
    __syncthreads();
    if (t < G_ && t < nact) {
        int p = col4row[t];
        if (p >= 0) { oi[p] = (float)t; om[p] = 1.0f; }
    }
}

// ---------------------------------------------------------------------------
static const int MATCHER_SMEM =
    G_ * 8                     /* rowarg_s */
    + P_ * 4 * 3               /* row4col, sh_dump, path_dump/colowner */
    + G_ * 4 * 2               /* u, col4row */
    + 2 * NW * 16              /* uint4 partials */
    + G_ + 64;                 /* SR + pad */

extern "C" void kernel_launch(void* const* d_in, const int* in_sizes, int n_in,
                              void* d_out, int out_size) {
    const float* cd   = (const float*)d_in[0];
    const float* gi   = (const float*)d_in[1];
    const int*   nact = (const int*)d_in[2];

    float* out = (float*)d_out;                  // [2, B, P] float32

    dim3 tb(32, 8);
    dim3 gb(P_ / 32, G_ / 32, B_);
    cost_transpose_kernel<<<gb, tb>>>(cd, gi);

    cudaFuncSetAttribute(matcher_kernel,
                         cudaFuncAttributeMaxDynamicSharedMemorySize, MATCHER_SMEM);
    matcher_kernel<<<B_, NT, MATCHER_SMEM>>>(nact, out);
}

// round 10
// speedup vs baseline: 1.4391x; 1.0543x over previous
#include <cuda_runtime.h>
#include <cuda_bf16.h>

#define B_ 8
#define P_ 4096
#define G_ 96
#define NT 256
#define NW (NT / 32)
#define CPT (P_ / NT)
#define PBLK 128                /* p-tiles of 32 in transpose */
#define BIGF 1e9f
#define INFF 3.402823466e+38f

__device__ float g_costT[(size_t)B_ * G_ * P_];
__device__ unsigned long long g_part[(size_t)B_ * G_ * PBLK]; // per-tile packed mins

__device__ __forceinline__ unsigned int f2ord(float f) {
    unsigned int u = __float_as_uint(f);
    return ((int)u < 0) ? ~u : (u ^ 0x80000000u);
}
__device__ __forceinline__ float ord2f(unsigned int k) {
    unsigned int u = (k & 0x80000000u) ? (k ^ 0x80000000u) : ~k;
    return __uint_as_float(u);
}

// ---------------------------------------------------------------------------
// Kernel 1: fused cost + transpose (32x32 tile, 4 elems/thread) + per-tile
// row-min partials.  costT[b][g][p] = cd[b][p][g] - 2*gi[b][p][g]
// ---------------------------------------------------------------------------
__global__ __launch_bounds__(256, 8)
void cost_transpose_kernel(const float* __restrict__ cd,
                           const float* __restrict__ gi) {
    __shared__ float tile[32][33];
    __shared__ unsigned long long pmin[32][8];
    const int b  = blockIdx.z;
    const int p0 = blockIdx.x * 32;
    const int g0 = blockIdx.y * 32;
    const int tx = threadIdx.x;              // g lane
    const int ty = threadIdx.y;              // p lane (0..7)

    float c[4], g[4];
    #pragma unroll
    for (int r = 0; r < 4; r++) {
        size_t iidx = ((size_t)b * P_ + (p0 + ty + 8 * r)) * G_ + (g0 + tx);
        c[r] = __ldg(cd + iidx);
        g[r] = __ldg(gi + iidx);
    }
    float bestv = INFF;
    int   bestp = 0;
    #pragma unroll
    for (int r = 0; r < 4; r++) {
        float val = c[r] - 2.0f * g[r];      // 2*g exact in fp32
        tile[ty + 8 * r][tx] = val;
        if (val < bestv) { bestv = val; bestp = p0 + ty + 8 * r; } // ascending p
    }
    pmin[tx][ty] = ((unsigned long long)f2ord(bestv) << 32) | (unsigned int)bestp;
    __syncthreads();

    #pragma unroll
    for (int r = 0; r < 4; r++)
        g_costT[((size_t)b * G_ + (g0 + ty + 8 * r)) * P_ + (p0 + tx)]
            = tile[tx][ty + 8 * r];

    if (ty == 0) {
        unsigned long long m = pmin[tx][0];
        #pragma unroll
        for (int w = 1; w < 8; w++) if (pmin[tx][w] < m) m = pmin[tx][w];
        g_part[((size_t)b * G_ + (g0 + tx)) * PBLK + blockIdx.x] = m;
    }

#if __CUDA_ARCH__ >= 900
    cudaTriggerProgrammaticLaunchCompletion();
#endif
}

// ---------------------------------------------------------------------------
// Kernel 2: one block per batch.  PDL: transpose-independent prologue first,
// then cudaGridDependencySynchronize(), then partial-reduce + greedy + JV.
// ---------------------------------------------------------------------------
__global__ __launch_bounds__(NT, 1)
void matcher_kernel(const int* __restrict__ nactual,
                    float* __restrict__ out) {
    extern __shared__ char smem[];
    unsigned long long* rowarg_s = (unsigned long long*)smem;   // [G_]
    int*   row4col  = (int*)(rowarg_s + G_);           // [P_]
    float* sh_dump  = (float*)(row4col + P_);          // [P_]
    int*   path_dump= (int*)(sh_dump + P_);            // [P_] (aliased as colowner)
    float* u        = (float*)(path_dump + P_);        // [G_]
    int*   col4row  = (int*)(u + G_);                  // [G_]
    uint4* partials = (uint4*)(col4row + G_);          // [2][NW]
    unsigned char* SR = (unsigned char*)(partials + 2 * NW); // [G_]

    const int b = blockIdx.x;
    const int t = threadIdx.x;
    const int wid = t >> 5, lane = t & 31;
    const float* cost = g_costT + (size_t)b * G_ * P_;
    const int nact = nactual[b];

    float vreg[CPT];
    float shreg[CPT];
    int   pathreg[CPT];
    unsigned int scmask;

    // ---- prologue: everything independent of the transpose ----
    float* oi = out + (size_t)b * P_;
    float* om = out + (size_t)B_ * P_ + (size_t)b * P_;
    #pragma unroll
    for (int k = 0; k < CPT; k++) vreg[k] = 0.0f;
    int* colowner = path_dump;
    for (int j = t; j < P_; j += NT) {
        row4col[j] = -1; colowner[j] = 0x7fffffff;
        oi[j] = 0.0f; om[j] = 0.0f;
    }
    if (t < G_) col4row[t] = -1;

#if __CUDA_ARCH__ >= 900
    cudaGridDependencySynchronize();       // wait for transpose results
#endif

    // (a) reduce partials: 8 warps x 12 rows
    #pragma unroll
    for (int rr = 0; rr < G_ / NW; rr++) {
        const int row = wid * (G_ / NW) + rr;
        const unsigned long long* pp = g_part + ((size_t)b * G_ + row) * PBLK;
        unsigned long long m = pp[lane];
        #pragma unroll
        for (int l = 1; l < PBLK / 32; l++) {
            unsigned long long o = pp[lane + 32 * l];
            if (o < m) m = o;
        }
        #pragma unroll
        for (int off = 16; off; off >>= 1) {
            unsigned long long o = __shfl_down_sync(0xffffffffu, m, off);
            if (o < m) m = o;
        }
        if (lane == 0) rowarg_s[row] = m;
    }
    __syncthreads();

    // (b) greedy: row i wants its argmin column; lowest row index wins
    unsigned long long myarg = 0;
    if (t < G_ && t < nact) {
        myarg = rowarg_s[t];
        u[t] = ord2f((unsigned int)(myarg >> 32));     // u[i] = row min (exact)
        atomicMin(&colowner[(int)(myarg & 0xffffffffu)], t);
    }
    __syncthreads();
    if (t < G_ && t < nact) {
        int j = (int)(myarg & 0xffffffffu);
        if (colowner[j] == t) { col4row[t] = j; row4col[j] = t; }
    }
    __syncthreads();

    // (c) augment the (rare) unassigned rows
    for (int i = 0; i < nact; ++i) {
        if (col4row[i] >= 0) continue;

        #pragma unroll
        for (int k = 0; k < CPT; k++) { shreg[k] = BIGF; pathreg[k] = -1; }
        scmask = 0u;
        if (t < G_) SR[t] = 0;
        __syncthreads();           // barrier A

        int   cur    = i;
        float ucur   = u[i];
        float minval = 0.0f;
        int   sink   = -1;
        int   parity = 0;

        while (sink < 0) {
            if (t == 0) SR[cur] = 1;
            const float* crow = cost + (size_t)cur * P_;

            float c[CPT];
            #pragma unroll
            for (int k = 0; k < CPT; k++) c[k] = __ldg(crow + t + k * NT);

            float bestv = INFF;
            int   bestj = P_;
            #pragma unroll
            for (int k = 0; k < CPT; k++) {
                if (!((scmask >> k) & 1u)) {
                    float red = ((minval + c[k]) - ucur) - vreg[k];
                    if (red < shreg[k]) { shreg[k] = red; pathreg[k] = cur; }
                    if (shreg[k] < bestv) { bestv = shreg[k]; bestj = t + k * NT; }
                }
            }
            unsigned int key    = f2ord(bestv);
            unsigned int minkey = __reduce_min_sync(0xffffffffu, key);
            unsigned int jc     = (key == minkey) ? (unsigned int)bestj : 0xffffffffu;
            unsigned int minj   = __reduce_min_sync(0xffffffffu, jc);

            if (lane == 0) {
                int r = row4col[minj];
                float ur = (r >= 0) ? u[r] : 0.0f;
                partials[parity * NW + wid] =
                    make_uint4(minkey, minj, (unsigned int)r, __float_as_uint(ur));
            }
            __syncthreads();

            uint4 best = partials[parity * NW];
            #pragma unroll
            for (int w = 1; w < NW; w++) {
                uint4 pw = partials[parity * NW + w];
                if (pw.x < best.x || (pw.x == best.x && pw.y < best.y)) best = pw;
            }
            minval = ord2f(best.x);
            int bj = (int)best.y;
            if ((bj & (NT - 1)) == t) scmask |= 1u << (bj >> 8);
            if ((int)best.z < 0) { sink = bj; }
            else { cur = (int)best.z; ucur = __uint_as_float(best.w); }
            parity ^= 1;
        }

        #pragma unroll
        for (int k = 0; k < CPT; k++) {
            sh_dump[t + k * NT]   = shreg[k];
            path_dump[t + k * NT] = pathreg[k];
        }
        __syncthreads();           // barrier B

        if (t == 0) u[i] += minval;
        if (t < G_ && t != i && SR[t]) {
            int c4 = col4row[t]; if (c4 < 0) c4 = 0;
            u[t] = (u[t] + minval) - sh_dump[c4];
        }
        #pragma unroll
        for (int k = 0; k < CPT; k++)
            if ((scmask >> k) & 1u) vreg[k] = vreg[k] - (minval - shreg[k]);
        __syncthreads();           // barrier C

        if (t == 0) {
            int j = sink;
            while (true) {
                int r = path_dump[j];
                row4col[j] = r;
                int jn = col4row[r];
                col4row[r] = j;
                if (r == i) break;
                j = jn;
            }
        }
        __syncthreads();
    }

    // final scatter (outputs already zeroed in prologue; barriers above order
    // all col4row writes before these reads)
    if (t < G_ && t < nact) {
        int p = col4row[t];
        if (p >= 0) { oi[p] = (float)t; om[p] = 1.0f; }
    }
}

// ---------------------------------------------------------------------------
static const int MATCHER_SMEM =
    G_ * 8                     /* rowarg_s */
    + P_ * 4 * 3               /* row4col, sh_dump, path_dump/colowner */
    + G_ * 4 * 2               /* u, col4row */
    + 2 * NW * 16              /* uint4 partials */
    + G_ + 64;                 /* SR + pad */

extern "C" void kernel_launch(void* const* d_in, const int* in_sizes, int n_in,
                              void* d_out, int out_size) {
    const float* cd   = (const float*)d_in[0];
    const float* gi   = (const float*)d_in[1];
    const int*   nact = (const int*)d_in[2];

    float* out = (float*)d_out;                  // [2, B, P] float32

    dim3 tb(32, 8);
    dim3 gb(P_ / 32, G_ / 32, B_);
    cost_transpose_kernel<<<gb, tb>>>(cd, gi);

    cudaFuncSetAttribute(matcher_kernel,
                         cudaFuncAttributeMaxDynamicSharedMemorySize, MATCHER_SMEM);

    cudaLaunchConfig_t cfg = {};
    cfg.gridDim = dim3(B_);
    cfg.blockDim = dim3(NT);
    cfg.dynamicSmemBytes = MATCHER_SMEM;
    cfg.stream = 0;
    cudaLaunchAttribute attr[1];
    attr[0].id = cudaLaunchAttributeProgrammaticStreamSerialization;
    attr[0].val.programmaticStreamSerializationAllowed = 1;
    cfg.attrs = attr;
    cfg.numAttrs = 1;
    cudaLaunchKernelEx(&cfg, matcher_kernel, nact, out);
}